// round 10
// baseline (speedup 1.0000x reference)
#include <cuda_runtime.h>
#include <cuda_bf16.h>
#include <cstdint>

#define NPTS 8192
#define D 200
#define ROW_BYTES 512              // bf16 rows zero-padded to 256 k in global
#define TMM 128                    // CTA tile rows (m)
#define TNN 64                     // CTA tile cols (n)
#define NTI (NPTS / TMM)           // 64
#define NTJ (NPTS / TNN)           // 128
#define NTILES 4160                // sum over ti of (NTJ - 2*ti)
#define TPB 256
#define SROW 144                   // padded smem row stride (conflict-free ldmatrix)
#define ACH (TMM * SROW)           // 18432
#define BCH (TNN * SROW)           // 9216
#define STAGE (ACH + BCH)          // 27648
#define SMEM_DYN (2 * STAGE)       // 55296

// ---------------- device scratch (no allocations allowed) ----------------
__device__ __align__(16) unsigned char g_xb[(size_t)NPTS * ROW_BYTES]; // 4 MB bf16
__device__ float g_sq[NPTS];
__device__ float g_part[NTILES];
__device__ int   g_is64;
__device__ unsigned int g_cnt;

#define CP16(d, s) \
    asm volatile("cp.async.cg.shared.global [%0], [%1], 16;" :: "r"(d), "l"(s) : "memory")
#define CPC()  asm volatile("cp.async.commit_group;" ::: "memory")
#define CPW1() asm volatile("cp.async.wait_group 1;" ::: "memory")
#define CPW0() asm volatile("cp.async.wait_group 0;" ::: "memory")

// ---------------------------------------------------------------------------
// Kernel 1: x -> bf16 (zero-padded), sq from the SAME bf16 values.
// Block 0 additionally: label-dtype detection + counter reset.
// ---------------------------------------------------------------------------
__global__ void prep_kernel(const float* __restrict__ x,
                            const int* __restrict__ lab32) {
    int row  = blockIdx.x * (TPB / 32) + (threadIdx.x >> 5);
    int lane = threadIdx.x & 31;
    int k0   = lane * 8;
    const float* xr = x + (size_t)row * D;
    float s = 0.f;
    uint32_t w[4];
#pragma unroll
    for (int p = 0; p < 4; p++) {
        int ka = k0 + 2 * p, kb = ka + 1;
        float f0 = (ka < D) ? xr[ka] : 0.f;
        float f1 = (kb < D) ? xr[kb] : 0.f;
        __nv_bfloat16 b0 = __float2bfloat16(f0);
        __nv_bfloat16 b1 = __float2bfloat16(f1);
        float g0 = __bfloat162float(b0), g1 = __bfloat162float(b1);
        s = fmaf(g0, g0, s);
        s = fmaf(g1, g1, s);
        w[p] = (uint32_t)__bfloat16_as_ushort(b0) |
               ((uint32_t)__bfloat16_as_ushort(b1) << 16);
    }
    *(uint4*)(g_xb + (size_t)row * ROW_BYTES + k0 * 2) = make_uint4(w[0], w[1], w[2], w[3]);
#pragma unroll
    for (int o = 16; o; o >>= 1) s += __shfl_xor_sync(0xffffffffu, s, o);
    if (lane == 0) g_sq[row] = s;

    if (blockIdx.x == 0) {  // label dtype detection + counter reset
        __shared__ int any;
        if (threadIdx.x == 0) { any = 0; g_cnt = 0; }
        __syncthreads();
        int a = 0;
        for (int i = 2 * threadIdx.x + 1; i < NPTS; i += 2 * TPB) a |= lab32[i];
        if (a) atomicOr(&any, 1);
        __syncthreads();
        if (threadIdx.x == 0) g_is64 = (any == 0) ? 1 : 0;
    }
}

// ---------------------------------------------------------------------------
// Chunk prefetch: 128B of K per row; A(128 rows) + B(64 rows) = 1536 16B loads.
// ---------------------------------------------------------------------------
__device__ __forceinline__ void prefetch(uint32_t dynA, int buf,
                                         const unsigned char* gA,
                                         const unsigned char* gB, int ch, int t) {
    uint32_t so = (buf ? STAGE : 0u);
#pragma unroll
    for (int p = 0; p < 6; p++) {
        int G = t + TPB * p;                 // 0..1535
        int isB  = (G >= 1024);
        int L    = isB ? (G - 1024) : G;
        int row  = L >> 3, g = L & 7;
        const unsigned char* gp = isB ? gB : gA;
        uint32_t soff = so + (isB ? ACH : 0u) + row * SROW + g * 16;
        size_t   goff = (size_t)row * ROW_BYTES + (size_t)ch * 128 + (size_t)g * 16;
        CP16(dynA + soff, gp + goff);
    }
    CPC();
}

// ---------------------------------------------------------------------------
// Kernel 2: 128x64 Gram tiles (3 CTAs/SM), mma.sync bf16 m16n8k16,
// warp tile 32x32, cp.async double buffer, 13 k-steps (K=208).
// ---------------------------------------------------------------------------
__global__ void __launch_bounds__(TPB, 3)
pair_kernel(const int* __restrict__ lab32, float* __restrict__ out) {
    extern __shared__ __align__(128) unsigned char dyn[];
    __shared__ float sqA[TMM], sqB[TNN];
    __shared__ int   lA[TMM], lB[TNN];
    __shared__ float red[TPB / 32];
    __shared__ int    s_last;
    __shared__ double dred[TPB];

    const int t    = threadIdx.x;
    const int wid  = t >> 5;
    const int lane = t & 31;

    // tile map: keep (ti, tj) with tj*64+63 > ti*128  <=>  tj >= 2*ti
    int bl = blockIdx.x, ti = 0;
    while (bl >= NTJ - 2 * ti) { bl -= NTJ - 2 * ti; ti++; }
    const int tj = 2 * ti + bl;

    const uint32_t dynA = (uint32_t)__cvta_generic_to_shared(dyn);
    const unsigned char* gA = g_xb + (size_t)(ti * TMM) * ROW_BYTES;
    const unsigned char* gB = g_xb + (size_t)(tj * TNN) * ROW_BYTES;

    prefetch(dynA, 0, gA, gB, 0, t);
    prefetch(dynA, 1, gA, gB, 1, t);

    {
        int is64 = g_is64;
        if (t < TMM) {
            int g = ti * TMM + t;
            sqA[t] = g_sq[g];
            lA[t]  = is64 ? lab32[2 * g] : lab32[g];
        } else if (t < TMM + TNN) {
            int u = t - TMM, g = tj * TNN + u;
            sqB[u] = g_sq[g];
            lB[u]  = is64 ? lab32[2 * g] : lab32[g];
        }
    }

    const int warp_m = wid & 3;    // 0..3 -> 32 m-rows
    const int warp_n = wid >> 2;   // 0..1 -> 32 n-cols

    uint32_t abase[2];
#pragma unroll
    for (int f = 0; f < 2; f++)
        abase[f] = dynA + (warp_m * 32 + f * 16 + (lane & 15)) * SROW
                 + ((lane >> 4) << 4);             // + a k-group 16B
    uint32_t bbase[2];
#pragma unroll
    for (int h = 0; h < 2; h++)
        bbase[h] = dynA + ACH
                 + (warp_n * 32 + h * 16 + (lane & 7) + ((lane >> 4) << 3)) * SROW
                 + (((lane >> 3) & 1) << 4);       // + b k-group 16B

    float acc[2][4][4];
#pragma unroll
    for (int f = 0; f < 2; f++)
#pragma unroll
        for (int j = 0; j < 4; j++)
#pragma unroll
            for (int e = 0; e < 4; e++) acc[f][j][e] = 0.f;

#define KSTEP(kk) do {                                                           \
    uint32_t a_[2][4];                                                           \
    _Pragma("unroll")                                                            \
    for (int f = 0; f < 2; f++)                                                  \
        asm volatile("ldmatrix.sync.aligned.m8n8.x4.shared.b16 {%0,%1,%2,%3}, [%4];" \
            : "=r"(a_[f][0]), "=r"(a_[f][1]), "=r"(a_[f][2]), "=r"(a_[f][3])     \
            : "r"(abase[f] + bofs + (kk) * 32));                                 \
    _Pragma("unroll")                                                            \
    for (int h = 0; h < 2; h++) {                                                \
        uint32_t b0_, b1_, b2_, b3_;                                             \
        asm volatile("ldmatrix.sync.aligned.m8n8.x4.shared.b16 {%0,%1,%2,%3}, [%4];" \
            : "=r"(b0_), "=r"(b1_), "=r"(b2_), "=r"(b3_)                         \
            : "r"(bbase[h] + bofs + (kk) * 32));                                 \
        _Pragma("unroll")                                                        \
        for (int f = 0; f < 2; f++) {                                            \
            asm volatile(                                                        \
                "mma.sync.aligned.m16n8k16.row.col.f32.bf16.bf16.f32 "           \
                "{%0,%1,%2,%3}, {%4,%5,%6,%7}, {%8,%9}, {%0,%1,%2,%3};"          \
                : "+f"(acc[f][2 * h][0]), "+f"(acc[f][2 * h][1]),                \
                  "+f"(acc[f][2 * h][2]), "+f"(acc[f][2 * h][3])                 \
                : "r"(a_[f][0]), "r"(a_[f][1]), "r"(a_[f][2]), "r"(a_[f][3]),    \
                  "r"(b0_), "r"(b1_));                                           \
            asm volatile(                                                        \
                "mma.sync.aligned.m16n8k16.row.col.f32.bf16.bf16.f32 "           \
                "{%0,%1,%2,%3}, {%4,%5,%6,%7}, {%8,%9}, {%0,%1,%2,%3};"          \
                : "+f"(acc[f][2 * h + 1][0]), "+f"(acc[f][2 * h + 1][1]),        \
                  "+f"(acc[f][2 * h + 1][2]), "+f"(acc[f][2 * h + 1][3])         \
                : "r"(a_[f][0]), "r"(a_[f][1]), "r"(a_[f][2]), "r"(a_[f][3]),    \
                  "r"(b2_), "r"(b3_));                                           \
        }                                                                        \
    }                                                                            \
} while (0)

#pragma unroll
    for (int ch = 0; ch < 4; ch++) {
        if (ch < 3) CPW1(); else CPW0();
        __syncthreads();
        const uint32_t bofs = (ch & 1) ? STAGE : 0u;
        KSTEP(0);
        if (ch < 3) { KSTEP(1); KSTEP(2); KSTEP(3); }  // 13 k-steps total
        __syncthreads();
        if (ch < 2) prefetch(dynA, ch & 1, gA, gB, ch + 2, t);
    }
#undef KSTEP

    // Epilogue: d2 -> dist -> signed, strict upper (gn > gm) predicate.
    float lsum = 0.f;
    const int qrow = lane >> 2;
    const int qcol = (lane & 3) * 2;
#pragma unroll
    for (int f = 0; f < 2; f++) {
        int m0 = warp_m * 32 + f * 16 + qrow;
#pragma unroll
        for (int j = 0; j < 4; j++) {
            int n0 = warp_n * 32 + j * 8 + qcol;
#pragma unroll
            for (int e = 0; e < 4; e++) {
                int m_loc = m0 + ((e >> 1) << 3);
                int n_loc = n0 + (e & 1);
                int gm = ti * TMM + m_loc;
                int gn = tj * TNN + n_loc;
                float d2   = sqA[m_loc] + sqB[n_loc] - 2.f * acc[f][j][e];
                float dist = sqrtf(fmaxf(d2, 0.f));
                float sgn  = (lA[m_loc] == lB[n_loc]) ? dist : -dist;
                if (gn > gm) lsum += sgn;
            }
        }
    }
#pragma unroll
    for (int o = 16; o; o >>= 1) lsum += __shfl_xor_sync(0xffffffffu, lsum, o);
    if (lane == 0) red[wid] = lsum;
    __syncthreads();
    if (t == 0) {
        float s = 0.f;
#pragma unroll
        for (int w = 0; w < TPB / 32; w++) s += red[w];
        g_part[blockIdx.x] = s;
    }

    // ---- last-CTA-done fused final reduction (deterministic order) ----
    __threadfence();
    if (t == 0) {
        unsigned old = atomicAdd(&g_cnt, 1u);
        s_last = (old == NTILES - 1) ? 1 : 0;
    }
    __syncthreads();
    if (s_last) {
        __threadfence();
        double a = 0.0;
        for (int i = t; i < NTILES; i += TPB) a += (double)g_part[i];
        dred[t] = a;
        __syncthreads();
        for (int o = TPB / 2; o; o >>= 1) {
            if (t < o) dred[t] += dred[t + o];
            __syncthreads();
        }
        if (t == 0) out[0] = (float)(2.0 * dred[0] / (double)NPTS);
    }
}

// ---------------------------------------------------------------------------
extern "C" void kernel_launch(void* const* d_in, const int* in_sizes, int n_in,
                              void* d_out, int out_size) {
    const float* x     = (const float*)d_in[0];
    const int*   lab32 = (const int*)d_in[1];
    float*       outp  = (float*)d_out;

    cudaFuncSetAttribute(pair_kernel, cudaFuncAttributeMaxDynamicSharedMemorySize,
                         SMEM_DYN);

    prep_kernel<<<NPTS / (TPB / 32), TPB>>>(x, lab32);
    pair_kernel<<<NTILES, TPB, SMEM_DYN>>>(lab32, outp);
}